// round 6
// baseline (speedup 1.0000x reference)
#include <cuda_runtime.h>

// Shapes (fixed per reference setup_inputs)
#define L_ 12
#define B_ 16
#define H_ 16
#define S_ 577
#define N_ 576      // spatial tokens (S-1)
#define D_ 1024
#define K_ 115      // int(576 * 0.2)

#define ROWS_ 4
#define CHUNKS_ ((K_ + ROWS_ - 1) / ROWS_)   // 29

// Scratch: top-k indices per batch (device global — no allocation allowed)
__device__ int g_topk[B_ * K_];

// ---------------------------------------------------------------------------
// Kernel 1: per-batch scores + exact top-K via rank counting.
// One block per batch, 576 threads. score[t] = sum_h attn[b,h,0,t+1].
// rank[t] = #{ j : sc[j] > sc[t]  or (==, j<t) } -> unique ranks, exactly
// matching jax.lax.top_k (desc value, asc index on ties).
// Rank loop vectorized: float4 shared loads, 144 iterations.
// ---------------------------------------------------------------------------
__global__ void topk_kernel(const float* __restrict__ attn) {
    __shared__ __align__(16) float sc[N_];
    const int b = blockIdx.x;
    const int t = threadIdx.x;

    if (t < N_) {
        float s = 0.0f;
        const float* base = attn + (size_t)b * H_ * S_ * S_ + (t + 1);
        #pragma unroll
        for (int h = 0; h < H_; ++h)
            s += __ldcs(base + (size_t)h * S_ * S_);
        sc[t] = s;
    }
    __syncthreads();

    if (t < N_) {
        const float my = sc[t];
        int rank = 0;
        const float4* sc4 = reinterpret_cast<const float4*>(sc);
        #pragma unroll 4
        for (int i = 0; i < N_ / 4; ++i) {
            const float4 v = sc4[i];
            const int j = 4 * i;
            rank += (v.x > my) || (v.x == my && (j + 0) < t);
            rank += (v.y > my) || (v.y == my && (j + 1) < t);
            rank += (v.z > my) || (v.z == my && (j + 2) < t);
            rank += (v.w > my) || (v.w == my && (j + 3) < t);
        }
        if (rank < K_)
            g_topk[b * K_ + rank] = t;
    }
}

// ---------------------------------------------------------------------------
// Kernel 2: gather selected K/V rows, 4 rows per block.
// Block handles rows [k0, k0+4) of one (l, b). 256 threads x float4 covers
// one 1024-float row. Loads batched before stores -> MLP 8 per thread.
// Streaming hints: data has zero reuse on both sides.
// ---------------------------------------------------------------------------
__global__ void gather_kernel(const float* __restrict__ key,
                              const float* __restrict__ val,
                              float* __restrict__ out) {
    const int chunk = blockIdx.x % CHUNKS_;
    const int b     = (blockIdx.x / CHUNKS_) % B_;
    const int l     = blockIdx.x / (CHUNKS_ * B_);
    const int k0    = chunk * ROWS_;
    const int t     = threadIdx.x;             // 0..255

    const size_t src_base = (((size_t)l * B_ + b) * S_) * D_;
    const size_t dst_base = (((size_t)l * B_ + b) * K_) * (size_t)D_;
    const size_t val_out_base = (size_t)L_ * B_ * K_ * D_;

    // Load the (up to 4) source indices — independent L2 hits.
    int src_s[ROWS_];
    #pragma unroll
    for (int r = 0; r < ROWS_; ++r) {
        const int k = k0 + r;
        src_s[r] = (k < K_) ? (g_topk[b * K_ + k] + 1) : -1;
    }

    // Batch all loads (up to 8 independent 16B loads in flight).
    float4 kr[ROWS_], vr[ROWS_];
    #pragma unroll
    for (int r = 0; r < ROWS_; ++r) {
        if (src_s[r] >= 0) {
            const float* ksrc = key + src_base + (size_t)src_s[r] * D_;
            const float* vsrc = val + src_base + (size_t)src_s[r] * D_;
            kr[r] = __ldcs(reinterpret_cast<const float4*>(ksrc) + t);
            vr[r] = __ldcs(reinterpret_cast<const float4*>(vsrc) + t);
        }
    }

    // Batch all stores.
    #pragma unroll
    for (int r = 0; r < ROWS_; ++r) {
        const int k = k0 + r;
        if (src_s[r] >= 0) {
            float* kdst = out + dst_base + (size_t)k * D_;
            float* vdst = out + val_out_base + dst_base + (size_t)k * D_;
            __stcs(reinterpret_cast<float4*>(kdst) + t, kr[r]);
            __stcs(reinterpret_cast<float4*>(vdst) + t, vr[r]);
        }
    }
}

extern "C" void kernel_launch(void* const* d_in, const int* in_sizes, int n_in,
                              void* d_out, int out_size) {
    const float* key  = (const float*)d_in[0];  // (12,16,577,1024) f32
    const float* val  = (const float*)d_in[1];  // (12,16,577,1024) f32
    const float* attn = (const float*)d_in[2];  // (16,16,577,577)  f32
    float* out = (float*)d_out;                 // keys then values, each (12,16,115,1024)

    topk_kernel<<<B_, N_>>>(attn);
    gather_kernel<<<L_ * B_ * CHUNKS_, 256>>>(key, val, out);
}

// round 8
// speedup vs baseline: 1.1652x; 1.1652x over previous
#include <cuda_runtime.h>

// Shapes (fixed per reference setup_inputs)
#define L_ 12
#define B_ 16
#define H_ 16
#define S_ 577
#define N_ 576      // spatial tokens (S-1)
#define D_ 1024
#define K_ 115      // int(576 * 0.2)

#define ROWS_ 4
#define CHUNKS_ ((K_ + ROWS_ - 1) / ROWS_)   // 29

#define SLICES_ 18                            // token slices per batch
#define SLICE_TOK_ 32                         // tokens per slice (18*32 = 576)
#define TPT_ 8                                // threads cooperating per token

// Scratch: top-k indices per batch (device global — no allocation allowed)
__device__ int g_topk[B_ * K_];

// ---------------------------------------------------------------------------
// Kernel 1: distributed exact top-K via rank counting.
// Grid = B*18 blocks, 256 threads. Block (b, s):
//   Phase 1: redundantly compute all 576 scores for batch b into shared
//            (identical sequential-h fp32 sum order in every block ->
//             bitwise-identical scores -> consistent ranks).
//   Phase 2: rank the 32 tokens of slice s; 8 threads split the 576
//            comparisons (72 each, stride 8 -> conflict-free LDS broadcast),
//            then shfl-reduce. rank < K  ->  g_topk[b*K + rank] = token.
// Comparator (v>my)||(v==my && j<t) reproduces jax.lax.top_k ordering
// (desc value, asc index on ties) with unique ranks -> no write races.
// ---------------------------------------------------------------------------
__global__ void topk_kernel(const float* __restrict__ attn) {
    __shared__ __align__(16) float sc[N_];
    const int b   = blockIdx.x / SLICES_;
    const int s   = blockIdx.x % SLICES_;
    const int tid = threadIdx.x;

    // Phase 1: scores for the whole batch (cooperative, 256 threads)
    const float* bbase = attn + (size_t)b * H_ * S_ * S_;
    for (int t = tid; t < N_; t += 256) {
        float sum = 0.0f;
        const float* p = bbase + (t + 1);
        #pragma unroll
        for (int h = 0; h < H_; ++h)
            sum += __ldg(p + (size_t)h * (S_ * S_));
        sc[t] = sum;
    }
    __syncthreads();

    // Phase 2: rank 32 tokens of this slice, 8 threads per token
    const int tok  = s * SLICE_TOK_ + (tid >> 3);   // tid/8 in 0..31
    const int part = tid & (TPT_ - 1);              // 0..7
    const float my = sc[tok];

    int rank = 0;
    #pragma unroll 8
    for (int j = part; j < N_; j += TPT_) {         // 72 iterations
        const float v = sc[j];
        rank += (v > my) || (v == my && j < tok);
    }
    // reduce across the 8-thread group (parts are adjacent lanes)
    #pragma unroll
    for (int off = TPT_ / 2; off > 0; off >>= 1)
        rank += __shfl_down_sync(0xffffffffu, rank, off, TPT_);

    if (part == 0 && rank < K_)
        g_topk[b * K_ + rank] = tok;
}

// ---------------------------------------------------------------------------
// Kernel 2: gather selected K/V rows, 4 rows per block (at HBM roofline).
// ---------------------------------------------------------------------------
__global__ void gather_kernel(const float* __restrict__ key,
                              const float* __restrict__ val,
                              float* __restrict__ out) {
    const int chunk = blockIdx.x % CHUNKS_;
    const int b     = (blockIdx.x / CHUNKS_) % B_;
    const int l     = blockIdx.x / (CHUNKS_ * B_);
    const int k0    = chunk * ROWS_;
    const int t     = threadIdx.x;             // 0..255

    const size_t src_base = (((size_t)l * B_ + b) * S_) * D_;
    const size_t dst_base = (((size_t)l * B_ + b) * K_) * (size_t)D_;
    const size_t val_out_base = (size_t)L_ * B_ * K_ * D_;

    int src_s[ROWS_];
    #pragma unroll
    for (int r = 0; r < ROWS_; ++r) {
        const int k = k0 + r;
        src_s[r] = (k < K_) ? (__ldg(&g_topk[b * K_ + k]) + 1) : -1;
    }

    float4 kr[ROWS_], vr[ROWS_];
    #pragma unroll
    for (int r = 0; r < ROWS_; ++r) {
        if (src_s[r] >= 0) {
            const float* ksrc = key + src_base + (size_t)src_s[r] * D_;
            const float* vsrc = val + src_base + (size_t)src_s[r] * D_;
            kr[r] = __ldcs(reinterpret_cast<const float4*>(ksrc) + t);
            vr[r] = __ldcs(reinterpret_cast<const float4*>(vsrc) + t);
        }
    }

    #pragma unroll
    for (int r = 0; r < ROWS_; ++r) {
        const int k = k0 + r;
        if (src_s[r] >= 0) {
            float* kdst = out + dst_base + (size_t)k * D_;
            float* vdst = out + val_out_base + dst_base + (size_t)k * D_;
            __stcs(reinterpret_cast<float4*>(kdst) + t, kr[r]);
            __stcs(reinterpret_cast<float4*>(vdst) + t, vr[r]);
        }
    }
}

extern "C" void kernel_launch(void* const* d_in, const int* in_sizes, int n_in,
                              void* d_out, int out_size) {
    const float* key  = (const float*)d_in[0];  // (12,16,577,1024) f32
    const float* val  = (const float*)d_in[1];  // (12,16,577,1024) f32
    const float* attn = (const float*)d_in[2];  // (16,16,577,577)  f32
    float* out = (float*)d_out;                 // keys then values, each (12,16,115,1024)

    topk_kernel<<<B_ * SLICES_, 256>>>(attn);
    gather_kernel<<<L_ * B_ * CHUNKS_, 256>>>(key, val, out);
}